// round 3
// baseline (speedup 1.0000x reference)
#include <cuda_runtime.h>
#include <math.h>

#define BATCH 2
#define SEQ   8192
#define DIM   512
#define BM    32          // K rows per block (output rows)
#define BN    128         // Q cols per tile
#define DSLICE 64         // d-slice for Q streaming
#define KS_STRIDE 36      // floats (pad: 16B aligned float4 rows, low conflict)
#define QS_STRIDE 132     // floats
#define PS_STRIDE 132     // u64 per row of ps[r][n]

typedef unsigned long long u64;

__device__ float g_K[BATCH * SEQ * DIM];
__device__ float g_Q[BATCH * SEQ * DIM];
__device__ float g_V[BATCH * SEQ * DIM];

// ---------------- packed f32x2 + shared-mem helpers ----------------
__device__ __forceinline__ unsigned smem_u32(const void* p) {
    unsigned r;
    asm("{ .reg .u64 t; cvta.to.shared.u64 t, %1; cvt.u32.u64 %0, t; }"
        : "=r"(r) : "l"(p));
    return r;
}
__device__ __forceinline__ u64 pack2(float lo, float hi) {
    u64 r; asm("mov.b64 %0, {%1, %2};" : "=l"(r) : "f"(lo), "f"(hi)); return r;
}
__device__ __forceinline__ void unpack2(u64 v, float& lo, float& hi) {
    asm("mov.b64 {%0, %1}, %2;" : "=f"(lo), "=f"(hi) : "l"(v));
}
__device__ __forceinline__ void fma2(u64& d, u64 a, u64 b) {
    asm("fma.rn.f32x2 %0, %1, %2, %0;" : "+l"(d) : "l"(a), "l"(b));
}
__device__ __forceinline__ void mul2(u64& d, u64 a) {
    asm("mul.rn.f32x2 %0, %0, %1;" : "+l"(d) : "l"(a));
}
__device__ __forceinline__ void lds_f4(float4& v, unsigned a) {
    asm volatile("ld.shared.v4.f32 {%0,%1,%2,%3}, [%4];"
                 : "=f"(v.x), "=f"(v.y), "=f"(v.z), "=f"(v.w) : "r"(a));
}
__device__ __forceinline__ void lds_2u64(u64& x, u64& y, unsigned a) {
    asm volatile("ld.shared.v2.u64 {%0,%1}, [%2];" : "=l"(x), "=l"(y) : "r"(a));
}
__device__ __forceinline__ u64 lds_u64(unsigned a) {
    u64 x; asm volatile("ld.shared.u64 %0, [%1];" : "=l"(x) : "r"(a)); return x;
}
__device__ __forceinline__ void sts_2u64(unsigned a, u64 x, u64 y) {
    asm volatile("st.shared.v2.u64 [%0], {%1,%2};" :: "r"(a), "l"(x), "l"(y));
}

// ---------------------------------------------------------------------------
// Projection GEMM: C[M][N] = X @ W^T + b  (unchanged from R1, ~0.8ms total)
// ---------------------------------------------------------------------------
__global__ __launch_bounds__(256) void proj_kernel(
    const float* __restrict__ X, const float* __restrict__ W,
    const float* __restrict__ bias, float* __restrict__ C)
{
    __shared__ float xs[16][68];
    __shared__ float ws[16][68];

    const int tx = threadIdx.x & 15;
    const int ty = threadIdx.x >> 4;
    const int m0 = blockIdx.y * 64;
    const int n0 = blockIdx.x * 64;
    const int lk = threadIdx.x & 15;
    const int lr = threadIdx.x >> 4;

    float acc[4][4] = {};

    for (int k0 = 0; k0 < DIM; k0 += 16) {
        #pragma unroll
        for (int i = 0; i < 4; i++) {
            int r = lr + i * 16;
            xs[lk][r] = X[(size_t)(m0 + r) * DIM + k0 + lk];
            ws[lk][r] = W[(size_t)(n0 + r) * DIM + k0 + lk];
        }
        __syncthreads();
        #pragma unroll
        for (int kk = 0; kk < 16; kk++) {
            float4 xv = *(const float4*)&xs[kk][ty * 4];
            float4 wv = *(const float4*)&ws[kk][tx * 4];
            float xr[4] = {xv.x, xv.y, xv.z, xv.w};
            float wr[4] = {wv.x, wv.y, wv.z, wv.w};
            #pragma unroll
            for (int r = 0; r < 4; r++)
                #pragma unroll
                for (int c = 0; c < 4; c++)
                    acc[r][c] += xr[r] * wr[c];
        }
        __syncthreads();
    }

    float4 bv = *(const float4*)&bias[n0 + tx * 4];
    float br[4] = {bv.x, bv.y, bv.z, bv.w};
    #pragma unroll
    for (int r = 0; r < 4; r++) {
        float4 ov;
        ov.x = acc[r][0] + br[0];
        ov.y = acc[r][1] + br[1];
        ov.z = acc[r][2] + br[2];
        ov.w = acc[r][3] + br[3];
        *(float4*)&C[(size_t)(m0 + ty * 4 + r) * DIM + n0 + tx * 4] = ov;
    }
}

// ---------------------------------------------------------------------------
// Flash attention, fp32 via packed fma.rn.f32x2 (FFMA2).
// Thread map: tx = lane (0..31) -> 4 cols / 4 d; ty = warp (0..7) -> 4 rows.
// ---------------------------------------------------------------------------
__global__ __launch_bounds__(256, 1) void attn_kernel(float* __restrict__ out)
{
    extern __shared__ float sm[];
    float* ks = sm;                              // [512][36]  K^T
    float* qs = ks + 512 * KS_STRIDE;            // [64][132]  Q slice (d-major)
    float* vs = qs + DSLICE * QS_STRIDE;         // [128][128] V chunk
    u64*   ps = (u64*)(vs + 128 * 128);          // [32][132]  P dup-pairs

    const int b  = blockIdx.y;
    const int m0 = blockIdx.x * BM;
    const float* Kp = g_K + (size_t)b * SEQ * DIM;
    const float* Qp = g_Q + (size_t)b * SEQ * DIM;
    const float* Vp = g_V + (size_t)b * SEQ * DIM;

    const int tid = threadIdx.x;
    const int tx  = tid & 31;
    const int ty  = tid >> 5;

    const unsigned ks_a = smem_u32(ks);
    const unsigned qs_a = smem_u32(qs);
    const unsigned vs_a = smem_u32(vs);
    const unsigned ps_a = smem_u32(ps);

    // K tile -> shared, transposed: ks[d][r]
    for (int idx = tid; idx < BM * DIM; idx += 256) {
        int r = idx >> 9;
        int d = idx & 511;
        ks[d * KS_STRIDE + r] = Kp[(size_t)(m0 + r) * DIM + d];
    }

    u64 o2[4][4][2] = {};            // [chunk][row][dpair]
    float mrow[4] = {-INFINITY, -INFINITY, -INFINITY, -INFINITY};
    float lrow[4] = {0.f, 0.f, 0.f, 0.f};

    const unsigned k_base = ks_a + ty * 16;      // float4 @ rows ty*4
    const unsigned q_base = qs_a + tx * 16;      // float4 @ cols tx*4
    const unsigned v_base = vs_a + tx * 16;

    for (int n0 = 0; n0 < SEQ; n0 += BN) {
        // ---- Phase A: S(32x128) = K_tile @ Q_tile^T ----
        u64 s2[4][2] = {};
        for (int sl = 0; sl < DIM / DSLICE; sl++) {
            int d0 = sl * DSLICE;
            __syncthreads();   // previous consumers of qs (and Phase C) done
            #pragma unroll
            for (int i = 0; i < DSLICE * BN / 256; i++) {   // 32
                int idx = tid + i * 256;
                int dd = idx & 63;
                int c  = idx >> 6;
                qs[dd * QS_STRIDE + c] = Qp[(size_t)(n0 + c) * DIM + d0 + dd];
            }
            __syncthreads();
            #pragma unroll 8
            for (int dd = 0; dd < DSLICE; dd++) {
                float4 kv;
                lds_f4(kv, k_base + (unsigned)((d0 + dd) * KS_STRIDE * 4));
                u64 q01, q23;
                lds_2u64(q01, q23, q_base + (unsigned)(dd * QS_STRIDE * 4));
                u64 k0 = pack2(kv.x, kv.x);
                u64 k1 = pack2(kv.y, kv.y);
                u64 k2 = pack2(kv.z, kv.z);
                u64 k3 = pack2(kv.w, kv.w);
                fma2(s2[0][0], k0, q01); fma2(s2[0][1], k0, q23);
                fma2(s2[1][0], k1, q01); fma2(s2[1][1], k1, q23);
                fma2(s2[2][0], k2, q01); fma2(s2[2][1], k2, q23);
                fma2(s2[3][0], k3, q01); fma2(s2[3][1], k3, q23);
            }
        }

        // ---- Phase B: online softmax, write P (duplicated pairs) ----
        float s[4][4];
        #pragma unroll
        for (int r = 0; r < 4; r++) {
            unpack2(s2[r][0], s[r][0], s[r][1]);
            unpack2(s2[r][1], s[r][2], s[r][3]);
        }
        #pragma unroll
        for (int r = 0; r < 4; r++) {
            float mx = fmaxf(fmaxf(s[r][0], s[r][1]), fmaxf(s[r][2], s[r][3]));
            #pragma unroll
            for (int off = 16; off > 0; off >>= 1)
                mx = fmaxf(mx, __shfl_xor_sync(0xffffffffu, mx, off));
            if (mx > mrow[r]) {
                float corr = __expf(mrow[r] - mx);   // 0 on first tile
                lrow[r] *= corr;
                u64 c2 = pack2(corr, corr);
                #pragma unroll
                for (int ch = 0; ch < 4; ch++) {
                    mul2(o2[ch][r][0], c2);
                    mul2(o2[ch][r][1], c2);
                }
                mrow[r] = mx;
            }
            float p0 = __expf(s[r][0] - mrow[r]);
            float p1 = __expf(s[r][1] - mrow[r]);
            float p2 = __expf(s[r][2] - mrow[r]);
            float p3 = __expf(s[r][3] - mrow[r]);
            float rs = (p0 + p1) + (p2 + p3);
            #pragma unroll
            for (int off = 16; off > 0; off >>= 1)
                rs += __shfl_xor_sync(0xffffffffu, rs, off);
            lrow[r] += rs;
            // ps[r_global][n_local] duplicated pairs; 2x st.v2.u64
            unsigned pa = ps_a + (unsigned)(((ty * 4 + r) * PS_STRIDE + tx * 4) * 8);
            sts_2u64(pa,      pack2(p0, p0), pack2(p1, p1));
            sts_2u64(pa + 16, pack2(p2, p2), pack2(p3, p3));
        }

        // ---- Phase C: O += P @ V, 4 chunks of 128 d ----
        #pragma unroll 1
        for (int ch = 0; ch < 4; ch++) {
            __syncthreads();   // ps ready / vs consumers done
            #pragma unroll
            for (int i = 0; i < 16; i++) {
                int n = ty + 8 * i;
                *(float4*)&vs[n * 128 + tx * 4] =
                    *(const float4*)&Vp[(size_t)(n0 + n) * DIM + ch * 128 + tx * 4];
            }
            __syncthreads();
            #pragma unroll 8
            for (int n = 0; n < BN; n++) {
                u64 v01, v23;
                lds_2u64(v01, v23, v_base + (unsigned)(n * 128 * 4));
                unsigned pb = ps_a + (unsigned)((ty * 4 * PS_STRIDE + n) * 8);
                u64 pA = lds_u64(pb);
                u64 pB = lds_u64(pb + PS_STRIDE * 8);
                u64 pC = lds_u64(pb + 2 * PS_STRIDE * 8);
                u64 pD = lds_u64(pb + 3 * PS_STRIDE * 8);
                fma2(o2[ch][0][0], pA, v01); fma2(o2[ch][0][1], pA, v23);
                fma2(o2[ch][1][0], pB, v01); fma2(o2[ch][1][1], pB, v23);
                fma2(o2[ch][2][0], pC, v01); fma2(o2[ch][2][1], pC, v23);
                fma2(o2[ch][3][0], pD, v01); fma2(o2[ch][3][1], pD, v23);
            }
        }
    }

    // ---- epilogue: out = O / l ----
    #pragma unroll
    for (int r = 0; r < 4; r++) {
        float inv = 1.f / lrow[r];
        size_t row = ((size_t)b * SEQ + m0 + ty * 4 + r) * DIM;
        #pragma unroll
        for (int ch = 0; ch < 4; ch++) {
            float a0, a1, a2, a3;
            unpack2(o2[ch][r][0], a0, a1);
            unpack2(o2[ch][r][1], a2, a3);
            float4 ov = {a0 * inv, a1 * inv, a2 * inv, a3 * inv};
            *(float4*)&out[row + ch * 128 + tx * 4] = ov;
        }
    }
}

__global__ void mask_kernel(float* __restrict__ p)
{
    p[threadIdx.x] = 0.f;
}

// ---------------------------------------------------------------------------
extern "C" void kernel_launch(void* const* d_in, const int* in_sizes, int n_in,
                              void* d_out, int out_size)
{
    (void)in_sizes; (void)n_in; (void)out_size;
    const float* x  = (const float*)d_in[0];
    const float* Wk = (const float*)d_in[1];
    const float* bk = (const float*)d_in[2];
    const float* Wq = (const float*)d_in[3];
    const float* bq = (const float*)d_in[4];
    const float* Wv = (const float*)d_in[5];
    const float* bv = (const float*)d_in[6];
    float* out = (float*)d_out;

    float *Kb, *Qb, *Vb;
    cudaGetSymbolAddress((void**)&Kb, g_K);
    cudaGetSymbolAddress((void**)&Qb, g_Q);
    cudaGetSymbolAddress((void**)&Vb, g_V);

    dim3 pgrid(DIM / 64, (BATCH * SEQ) / 64);
    proj_kernel<<<pgrid, 256>>>(x, Wk, bk, Kb);
    proj_kernel<<<pgrid, 256>>>(x, Wq, bq, Qb);
    proj_kernel<<<pgrid, 256>>>(x, Wv, bv, Vb);

    size_t smem = (size_t)(512 * KS_STRIDE + DSLICE * QS_STRIDE + 128 * 128) * sizeof(float)
                + (size_t)(32 * PS_STRIDE) * sizeof(u64);
    cudaFuncSetAttribute(attn_kernel, cudaFuncAttributeMaxDynamicSharedMemorySize,
                         (int)smem);
    attn_kernel<<<dim3(SEQ / BM, BATCH), 256, smem>>>(out);

    mask_kernel<<<1, 16>>>(out + (size_t)BATCH * SEQ * DIM);
}

// round 4
// speedup vs baseline: 1.0053x; 1.0053x over previous
#include <cuda_runtime.h>
#include <math.h>

#define BATCH 2
#define SEQ   8192
#define DIM   512
#define BM    32          // K rows per block (output rows)
#define BN    128         // Q cols per tile
#define DSLICE 64         // d-slice for Q streaming
#define KS_STRIDE 36      // floats (pad: 16B aligned float4 rows, low conflict)
#define QS_STRIDE 132     // floats
#define PS_STRIDE 132     // u64 per row of ps[r][n]

typedef unsigned long long u64;

__device__ float g_K[BATCH * SEQ * DIM];
__device__ float g_Q[BATCH * SEQ * DIM];
__device__ float g_V[BATCH * SEQ * DIM];

// ---------------- packed f32x2 + shared-mem helpers ----------------
__device__ __forceinline__ unsigned smem_u32(const void* p) {
    unsigned r;
    asm("{ .reg .u64 t; cvta.to.shared.u64 t, %1; cvt.u32.u64 %0, t; }"
        : "=r"(r) : "l"(p));
    return r;
}
__device__ __forceinline__ u64 pack2(float lo, float hi) {
    u64 r; asm("mov.b64 %0, {%1, %2};" : "=l"(r) : "f"(lo), "f"(hi)); return r;
}
__device__ __forceinline__ void unpack2(u64 v, float& lo, float& hi) {
    asm("mov.b64 {%0, %1}, %2;" : "=f"(lo), "=f"(hi) : "l"(v));
}
__device__ __forceinline__ void fma2(u64& d, u64 a, u64 b) {
    asm("fma.rn.f32x2 %0, %1, %2, %0;" : "+l"(d) : "l"(a), "l"(b));
}
__device__ __forceinline__ void mul2(u64& d, u64 a) {
    asm("mul.rn.f32x2 %0, %0, %1;" : "+l"(d) : "l"(a));
}
__device__ __forceinline__ void lds_f4(float4& v, unsigned a) {
    asm volatile("ld.shared.v4.f32 {%0,%1,%2,%3}, [%4];"
                 : "=f"(v.x), "=f"(v.y), "=f"(v.z), "=f"(v.w) : "r"(a));
}
__device__ __forceinline__ void lds_2u64(u64& x, u64& y, unsigned a) {
    asm volatile("ld.shared.v2.u64 {%0,%1}, [%2];" : "=l"(x), "=l"(y) : "r"(a));
}
__device__ __forceinline__ u64 lds_u64(unsigned a) {
    u64 x; asm volatile("ld.shared.u64 %0, [%1];" : "=l"(x) : "r"(a)); return x;
}
__device__ __forceinline__ void sts_2u64(unsigned a, u64 x, u64 y) {
    asm volatile("st.shared.v2.u64 [%0], {%1,%2};" :: "r"(a), "l"(x), "l"(y));
}

// ---------------------------------------------------------------------------
// Projection GEMM: C[M][N] = X @ W^T + b  (unchanged from R1, ~0.8ms total)
// ---------------------------------------------------------------------------
__global__ __launch_bounds__(256) void proj_kernel(
    const float* __restrict__ X, const float* __restrict__ W,
    const float* __restrict__ bias, float* __restrict__ C)
{
    __shared__ float xs[16][68];
    __shared__ float ws[16][68];

    const int tx = threadIdx.x & 15;
    const int ty = threadIdx.x >> 4;
    const int m0 = blockIdx.y * 64;
    const int n0 = blockIdx.x * 64;
    const int lk = threadIdx.x & 15;
    const int lr = threadIdx.x >> 4;

    float acc[4][4] = {};

    for (int k0 = 0; k0 < DIM; k0 += 16) {
        #pragma unroll
        for (int i = 0; i < 4; i++) {
            int r = lr + i * 16;
            xs[lk][r] = X[(size_t)(m0 + r) * DIM + k0 + lk];
            ws[lk][r] = W[(size_t)(n0 + r) * DIM + k0 + lk];
        }
        __syncthreads();
        #pragma unroll
        for (int kk = 0; kk < 16; kk++) {
            float4 xv = *(const float4*)&xs[kk][ty * 4];
            float4 wv = *(const float4*)&ws[kk][tx * 4];
            float xr[4] = {xv.x, xv.y, xv.z, xv.w};
            float wr[4] = {wv.x, wv.y, wv.z, wv.w};
            #pragma unroll
            for (int r = 0; r < 4; r++)
                #pragma unroll
                for (int c = 0; c < 4; c++)
                    acc[r][c] += xr[r] * wr[c];
        }
        __syncthreads();
    }

    float4 bv = *(const float4*)&bias[n0 + tx * 4];
    float br[4] = {bv.x, bv.y, bv.z, bv.w};
    #pragma unroll
    for (int r = 0; r < 4; r++) {
        float4 ov;
        ov.x = acc[r][0] + br[0];
        ov.y = acc[r][1] + br[1];
        ov.z = acc[r][2] + br[2];
        ov.w = acc[r][3] + br[3];
        *(float4*)&C[(size_t)(m0 + ty * 4 + r) * DIM + n0 + tx * 4] = ov;
    }
}

// ---------------------------------------------------------------------------
// Flash attention, fp32 via packed fma.rn.f32x2 (FFMA2).
// Thread map: tx = lane (0..31) -> 4 cols / 4 d; ty = warp (0..7) -> 4 rows.
// ---------------------------------------------------------------------------
__global__ __launch_bounds__(256, 1) void attn_kernel(float* __restrict__ out)
{
    extern __shared__ float sm[];
    float* ks = sm;                              // [512][36]  K^T
    float* qs = ks + 512 * KS_STRIDE;            // [64][132]  Q slice (d-major)
    float* vs = qs + DSLICE * QS_STRIDE;         // [128][128] V chunk
    u64*   ps = (u64*)(vs + 128 * 128);          // [32][132]  P dup-pairs

    const int b  = blockIdx.y;
    const int m0 = blockIdx.x * BM;
    const float* Kp = g_K + (size_t)b * SEQ * DIM;
    const float* Qp = g_Q + (size_t)b * SEQ * DIM;
    const float* Vp = g_V + (size_t)b * SEQ * DIM;

    const int tid = threadIdx.x;
    const int tx  = tid & 31;
    const int ty  = tid >> 5;

    const unsigned ks_a = smem_u32(ks);
    const unsigned qs_a = smem_u32(qs);
    const unsigned vs_a = smem_u32(vs);
    const unsigned ps_a = smem_u32(ps);

    // K tile -> shared, transposed: ks[d][r]
    for (int idx = tid; idx < BM * DIM; idx += 256) {
        int r = idx >> 9;
        int d = idx & 511;
        ks[d * KS_STRIDE + r] = Kp[(size_t)(m0 + r) * DIM + d];
    }

    u64 o2[4][4][2] = {};            // [chunk][row][dpair]
    float mrow[4] = {-INFINITY, -INFINITY, -INFINITY, -INFINITY};
    float lrow[4] = {0.f, 0.f, 0.f, 0.f};

    const unsigned k_base = ks_a + ty * 16;      // float4 @ rows ty*4
    const unsigned q_base = qs_a + tx * 16;      // float4 @ cols tx*4
    const unsigned v_base = vs_a + tx * 16;

    for (int n0 = 0; n0 < SEQ; n0 += BN) {
        // ---- Phase A: S(32x128) = K_tile @ Q_tile^T ----
        u64 s2[4][2] = {};
        for (int sl = 0; sl < DIM / DSLICE; sl++) {
            int d0 = sl * DSLICE;
            __syncthreads();   // previous consumers of qs (and Phase C) done
            #pragma unroll
            for (int i = 0; i < DSLICE * BN / 256; i++) {   // 32
                int idx = tid + i * 256;
                int dd = idx & 63;
                int c  = idx >> 6;
                qs[dd * QS_STRIDE + c] = Qp[(size_t)(n0 + c) * DIM + d0 + dd];
            }
            __syncthreads();
            #pragma unroll 8
            for (int dd = 0; dd < DSLICE; dd++) {
                float4 kv;
                lds_f4(kv, k_base + (unsigned)((d0 + dd) * KS_STRIDE * 4));
                u64 q01, q23;
                lds_2u64(q01, q23, q_base + (unsigned)(dd * QS_STRIDE * 4));
                u64 k0 = pack2(kv.x, kv.x);
                u64 k1 = pack2(kv.y, kv.y);
                u64 k2 = pack2(kv.z, kv.z);
                u64 k3 = pack2(kv.w, kv.w);
                fma2(s2[0][0], k0, q01); fma2(s2[0][1], k0, q23);
                fma2(s2[1][0], k1, q01); fma2(s2[1][1], k1, q23);
                fma2(s2[2][0], k2, q01); fma2(s2[2][1], k2, q23);
                fma2(s2[3][0], k3, q01); fma2(s2[3][1], k3, q23);
            }
        }

        // ---- Phase B: online softmax, write P (duplicated pairs) ----
        float s[4][4];
        #pragma unroll
        for (int r = 0; r < 4; r++) {
            unpack2(s2[r][0], s[r][0], s[r][1]);
            unpack2(s2[r][1], s[r][2], s[r][3]);
        }
        #pragma unroll
        for (int r = 0; r < 4; r++) {
            float mx = fmaxf(fmaxf(s[r][0], s[r][1]), fmaxf(s[r][2], s[r][3]));
            #pragma unroll
            for (int off = 16; off > 0; off >>= 1)
                mx = fmaxf(mx, __shfl_xor_sync(0xffffffffu, mx, off));
            if (mx > mrow[r]) {
                float corr = __expf(mrow[r] - mx);   // 0 on first tile
                lrow[r] *= corr;
                u64 c2 = pack2(corr, corr);
                #pragma unroll
                for (int ch = 0; ch < 4; ch++) {
                    mul2(o2[ch][r][0], c2);
                    mul2(o2[ch][r][1], c2);
                }
                mrow[r] = mx;
            }
            float p0 = __expf(s[r][0] - mrow[r]);
            float p1 = __expf(s[r][1] - mrow[r]);
            float p2 = __expf(s[r][2] - mrow[r]);
            float p3 = __expf(s[r][3] - mrow[r]);
            float rs = (p0 + p1) + (p2 + p3);
            #pragma unroll
            for (int off = 16; off > 0; off >>= 1)
                rs += __shfl_xor_sync(0xffffffffu, rs, off);
            lrow[r] += rs;
            // ps[r_global][n_local] duplicated pairs; 2x st.v2.u64
            unsigned pa = ps_a + (unsigned)(((ty * 4 + r) * PS_STRIDE + tx * 4) * 8);
            sts_2u64(pa,      pack2(p0, p0), pack2(p1, p1));
            sts_2u64(pa + 16, pack2(p2, p2), pack2(p3, p3));
        }

        // ---- Phase C: O += P @ V, 4 chunks of 128 d ----
        #pragma unroll 1
        for (int ch = 0; ch < 4; ch++) {
            __syncthreads();   // ps ready / vs consumers done
            #pragma unroll
            for (int i = 0; i < 16; i++) {
                int n = ty + 8 * i;
                *(float4*)&vs[n * 128 + tx * 4] =
                    *(const float4*)&Vp[(size_t)(n0 + n) * DIM + ch * 128 + tx * 4];
            }
            __syncthreads();
            #pragma unroll 8
            for (int n = 0; n < BN; n++) {
                u64 v01, v23;
                lds_2u64(v01, v23, v_base + (unsigned)(n * 128 * 4));
                unsigned pb = ps_a + (unsigned)((ty * 4 * PS_STRIDE + n) * 8);
                u64 pA = lds_u64(pb);
                u64 pB = lds_u64(pb + PS_STRIDE * 8);
                u64 pC = lds_u64(pb + 2 * PS_STRIDE * 8);
                u64 pD = lds_u64(pb + 3 * PS_STRIDE * 8);
                fma2(o2[ch][0][0], pA, v01); fma2(o2[ch][0][1], pA, v23);
                fma2(o2[ch][1][0], pB, v01); fma2(o2[ch][1][1], pB, v23);
                fma2(o2[ch][2][0], pC, v01); fma2(o2[ch][2][1], pC, v23);
                fma2(o2[ch][3][0], pD, v01); fma2(o2[ch][3][1], pD, v23);
            }
        }
    }

    // ---- epilogue: out = O / l ----
    #pragma unroll
    for (int r = 0; r < 4; r++) {
        float inv = 1.f / lrow[r];
        size_t row = ((size_t)b * SEQ + m0 + ty * 4 + r) * DIM;
        #pragma unroll
        for (int ch = 0; ch < 4; ch++) {
            float a0, a1, a2, a3;
            unpack2(o2[ch][r][0], a0, a1);
            unpack2(o2[ch][r][1], a2, a3);
            float4 ov = {a0 * inv, a1 * inv, a2 * inv, a3 * inv};
            *(float4*)&out[row + ch * 128 + tx * 4] = ov;
        }
    }
}

__global__ void mask_kernel(float* __restrict__ p)
{
    p[threadIdx.x] = 0.f;
}

// ---------------------------------------------------------------------------
extern "C" void kernel_launch(void* const* d_in, const int* in_sizes, int n_in,
                              void* d_out, int out_size)
{
    (void)in_sizes; (void)n_in; (void)out_size;
    const float* x  = (const float*)d_in[0];
    const float* Wk = (const float*)d_in[1];
    const float* bk = (const float*)d_in[2];
    const float* Wq = (const float*)d_in[3];
    const float* bq = (const float*)d_in[4];
    const float* Wv = (const float*)d_in[5];
    const float* bv = (const float*)d_in[6];
    float* out = (float*)d_out;

    float *Kb, *Qb, *Vb;
    cudaGetSymbolAddress((void**)&Kb, g_K);
    cudaGetSymbolAddress((void**)&Qb, g_Q);
    cudaGetSymbolAddress((void**)&Vb, g_V);

    dim3 pgrid(DIM / 64, (BATCH * SEQ) / 64);
    proj_kernel<<<pgrid, 256>>>(x, Wk, bk, Kb);
    proj_kernel<<<pgrid, 256>>>(x, Wq, bq, Qb);
    proj_kernel<<<pgrid, 256>>>(x, Wv, bv, Vb);

    size_t smem = (size_t)(512 * KS_STRIDE + DSLICE * QS_STRIDE + 128 * 128) * sizeof(float)
                + (size_t)(32 * PS_STRIDE) * sizeof(u64);
    cudaFuncSetAttribute(attn_kernel, cudaFuncAttributeMaxDynamicSharedMemorySize,
                         (int)smem);
    attn_kernel<<<dim3(SEQ / BM, BATCH), 256, smem>>>(out);

    mask_kernel<<<1, 16>>>(out + (size_t)BATCH * SEQ * DIM);
}